// round 1
// baseline (speedup 1.0000x reference)
#include <cuda_runtime.h>
#include <cstdint>

#define BATCH   2
#define DM      256
#define HH      64
#define WW      64
#define LSEQ    (HH*WW)          // 4096
#define DIN     512
#define DSTATE  16
#define DTR     16
#define DCONV   4
#define ROWS    (BATCH*LSEQ)     // 8192

// ---------------- scratch (device globals; no allocation allowed) ----------
__device__ float g_h  [ROWS*DM];        // LN1 output, (row, 256)
__device__ float g_xz [ROWS*2*DIN];     // in_proj output, (row, 1024): [0:512)=xm, [512:1024)=z
__device__ float g_xc [ROWS*DIN];       // conv+silu output
__device__ float g_dt [ROWS*DIN];       // softplus(dt)
__device__ float g_Bm [ROWS*DSTATE];
__device__ float g_Cm [ROWS*DSTATE];
__device__ float g_y  [ROWS*DIN];       // scan output (gated)
__device__ float g_mo [ROWS*DM];        // out_proj output

// ---------------- LN1: x (B,C,L) -> normed (row=b*L+l, 256) ----------------
__global__ void ln1_kernel(const float* __restrict__ x,
                           const float* __restrict__ w,
                           const float* __restrict__ bb) {
    __shared__ float sm[DM*33];
    int b  = blockIdx.x / (LSEQ/32);
    int l0 = (blockIdx.x % (LSEQ/32)) * 32;
    int tid = threadIdx.x;
    int li = tid & 31, c0 = tid >> 5;
    const float* xb = x + (size_t)b*DM*LSEQ;
    #pragma unroll
    for (int c = c0; c < DM; c += 8)
        sm[c*33 + li] = xb[(size_t)c*LSEQ + l0 + li];
    __syncthreads();
    int wid = tid >> 5, lane = tid & 31;
    for (int li2 = wid; li2 < 32; li2 += 8) {
        float s = 0.f, s2 = 0.f, v[8];
        #pragma unroll
        for (int k = 0; k < 8; k++) {
            v[k] = sm[(k*32+lane)*33 + li2];
            s += v[k]; s2 += v[k]*v[k];
        }
        #pragma unroll
        for (int o = 16; o > 0; o >>= 1) {
            s  += __shfl_xor_sync(0xffffffffu, s,  o);
            s2 += __shfl_xor_sync(0xffffffffu, s2, o);
        }
        float mu = s * (1.f/DM);
        float var = s2 * (1.f/DM) - mu*mu;
        float rs = rsqrtf(var + 1e-5f);
        float* orow = g_h + ((size_t)b*LSEQ + l0 + li2)*DM;
        #pragma unroll
        for (int k = 0; k < 8; k++) {
            int c = k*32 + lane;
            orow[c] = (v[k]-mu)*rs*w[c] + bb[c];
        }
    }
}

// ---------------- generic C[M,N] = A[M,K] @ W[N,K]^T ----------------
// BM=64, BN=64, BK=16, 256 threads, 4x4 per thread. M%64==0, N%64==0, K%16==0.
__global__ void gemm_abt(const float* __restrict__ A, const float* __restrict__ W,
                         float* __restrict__ C, int M, int N, int K) {
    __shared__ float As[16][65];
    __shared__ float Ws[16][65];
    int bm = blockIdx.y * 64, bn = blockIdx.x * 64;
    int tid = threadIdx.x;
    int tm = (tid >> 4) * 4;
    int tn = (tid & 15) * 4;
    float acc[4][4] = {};
    for (int k0 = 0; k0 < K; k0 += 16) {
        #pragma unroll
        for (int i = tid; i < 64*16; i += 256) {
            int m = i >> 4, k = i & 15;
            As[k][m] = A[(size_t)(bm+m)*K + k0 + k];
        }
        #pragma unroll
        for (int i = tid; i < 64*16; i += 256) {
            int n = i >> 4, k = i & 15;
            Ws[k][n] = W[(size_t)(bn+n)*K + k0 + k];
        }
        __syncthreads();
        #pragma unroll
        for (int k = 0; k < 16; k++) {
            float a[4], w[4];
            #pragma unroll
            for (int i = 0; i < 4; i++) a[i] = As[k][tm+i];
            #pragma unroll
            for (int j = 0; j < 4; j++) w[j] = Ws[k][tn+j];
            #pragma unroll
            for (int i = 0; i < 4; i++)
                #pragma unroll
                for (int j = 0; j < 4; j++)
                    acc[i][j] += a[i]*w[j];
        }
        __syncthreads();
    }
    #pragma unroll
    for (int i = 0; i < 4; i++)
        #pragma unroll
        for (int j = 0; j < 4; j++)
            C[(size_t)(bm+tm+i)*N + bn+tn+j] = acc[i][j];
}

// ---------------- depthwise causal conv(4) + bias + SiLU ----------------
__global__ void conv_kernel(const float* __restrict__ cw, const float* __restrict__ cb) {
    int r = blockIdx.x;           // b*L + l
    int d = threadIdx.x;          // 0..511
    int l = r & (LSEQ-1);
    float acc = cb[d];
    #pragma unroll
    for (int k = 0; k < DCONV; k++) {
        int ll = l - (DCONV-1) + k;
        if (ll >= 0)
            acc += cw[d*DCONV + k] * g_xz[((size_t)r - (DCONV-1) + k)*(2*DIN) + d];
    }
    float sv = acc / (1.f + expf(-acc));
    g_xc[(size_t)r*DIN + d] = sv;
}

// ---------------- x_proj (48x512) + dt_proj (512x16) + softplus ----------
__global__ void xproj_kernel(const float* __restrict__ xpw,
                             const float* __restrict__ dpw,
                             const float* __restrict__ dpb) {
    __shared__ float sx[DIN];
    __shared__ float sp[DTR + 2*DSTATE];
    int r = blockIdx.x;
    int tid = threadIdx.x;  // 256
    sx[tid]       = g_xc[(size_t)r*DIN + tid];
    sx[tid + 256] = g_xc[(size_t)r*DIN + tid + 256];
    __syncthreads();
    int wid = tid >> 5, lane = tid & 31;
    for (int o = wid; o < DTR + 2*DSTATE; o += 8) {
        float s = 0.f;
        const float* wr = xpw + (size_t)o*DIN;
        #pragma unroll 4
        for (int k = lane; k < DIN; k += 32) s += wr[k]*sx[k];
        #pragma unroll
        for (int off = 16; off > 0; off >>= 1) s += __shfl_xor_sync(0xffffffffu, s, off);
        if (lane == 0) sp[o] = s;
    }
    __syncthreads();
    for (int d = tid; d < DIN; d += 256) {
        float s = dpb[d];
        #pragma unroll
        for (int k = 0; k < DTR; k++) s += dpw[d*DTR + k]*sp[k];
        g_dt[(size_t)r*DIN + d] = (s > 20.f) ? s : log1pf(expf(s));
    }
    if (tid < DSTATE)       g_Bm[r*DSTATE + tid]        = sp[DTR + tid];
    else if (tid < 2*DSTATE) g_Cm[r*DSTATE + (tid-16)]  = sp[DTR + DSTATE + (tid-16)];
}

// ---------------- selective scan + gating ----------------
// lane layout: 16 lanes per (b,d) channel, lane = state index s
__global__ void scan_kernel(const float* __restrict__ A_log, const float* __restrict__ Dp) {
    int g = blockIdx.x * (blockDim.x >> 4) + (threadIdx.x >> 4);
    int s = threadIdx.x & 15;
    int b = g >> 9;        // g / 512
    int d = g & 511;
    float A  = -expf(A_log[d*DSTATE + s]);
    float Dd = Dp[d];
    float h = 0.f;
    size_t base = (size_t)b*LSEQ;
    for (int l = 0; l < LSEQ; l++) {
        size_t r = base + l;
        float dt = g_dt[r*DIN + d];
        float xv = g_xc[r*DIN + d];
        float Bv = g_Bm[r*DSTATE + s];
        float Cv = g_Cm[r*DSTATE + s];
        h = h*expf(dt*A) + dt*xv*Bv;
        float p = h*Cv;
        p += __shfl_xor_sync(0xffffffffu, p, 8, 16);
        p += __shfl_xor_sync(0xffffffffu, p, 4, 16);
        p += __shfl_xor_sync(0xffffffffu, p, 2, 16);
        p += __shfl_xor_sync(0xffffffffu, p, 1, 16);
        if (s == 0) {
            float z = g_xz[r*(2*DIN) + DIN + d];
            g_y[r*DIN + d] = (p + xv*Dd) * (z / (1.f + expf(-z)));
        }
    }
}

// ---------------- LN2 + residual + transpose back to (B,C,H,W) ----------
__global__ void ln2_kernel(const float* __restrict__ w, const float* __restrict__ bb,
                           const float* __restrict__ x, float* __restrict__ out) {
    __shared__ float sm[DM*33];
    int b  = blockIdx.x / (LSEQ/32);
    int l0 = (blockIdx.x % (LSEQ/32)) * 32;
    int tid = threadIdx.x;
    const float* mo = g_mo + ((size_t)b*LSEQ + l0)*DM;
    for (int i = tid; i < 32*DM; i += 256) {
        int li = i >> 8, c = i & 255;
        sm[c*33 + li] = mo[li*DM + c];
    }
    __syncthreads();
    int wid = tid >> 5, lane = tid & 31;
    for (int li2 = wid; li2 < 32; li2 += 8) {
        float s = 0.f, s2 = 0.f, v[8];
        #pragma unroll
        for (int k = 0; k < 8; k++) {
            v[k] = sm[(k*32+lane)*33 + li2];
            s += v[k]; s2 += v[k]*v[k];
        }
        #pragma unroll
        for (int o = 16; o > 0; o >>= 1) {
            s  += __shfl_xor_sync(0xffffffffu, s,  o);
            s2 += __shfl_xor_sync(0xffffffffu, s2, o);
        }
        float mu = s * (1.f/DM);
        float var = s2 * (1.f/DM) - mu*mu;
        float rs = rsqrtf(var + 1e-5f);
        #pragma unroll
        for (int k = 0; k < 8; k++) {
            int c = k*32 + lane;
            sm[c*33 + li2] = (v[k]-mu)*rs*w[c] + bb[c];
        }
    }
    __syncthreads();
    int li = tid & 31, c0 = tid >> 5;
    const float* xb = x + (size_t)b*DM*LSEQ;
    float* ob = out + (size_t)b*DM*LSEQ;
    #pragma unroll
    for (int c = c0; c < DM; c += 8) {
        size_t idx = (size_t)c*LSEQ + l0 + li;
        ob[idx] = xb[idx] + sm[c*33 + li];
    }
}

// ---------------- launch ----------------
extern "C" void kernel_launch(void* const* d_in, const int* in_sizes, int n_in,
                              void* d_out, int out_size) {
    const float* x        = (const float*)d_in[0];
    const float* ln1_w    = (const float*)d_in[1];
    const float* ln1_b    = (const float*)d_in[2];
    const float* ln2_w    = (const float*)d_in[3];
    const float* ln2_b    = (const float*)d_in[4];
    const float* in_proj  = (const float*)d_in[5];
    const float* conv_w   = (const float*)d_in[6];
    const float* conv_b   = (const float*)d_in[7];
    const float* x_proj   = (const float*)d_in[8];
    const float* dt_proj  = (const float*)d_in[9];
    const float* dt_bias  = (const float*)d_in[10];
    const float* A_log    = (const float*)d_in[11];
    const float* Dp       = (const float*)d_in[12];
    const float* out_proj = (const float*)d_in[13];
    float* out = (float*)d_out;

    float* g_h_p;  cudaGetSymbolAddress((void**)&g_h_p,  g_h);
    float* g_xz_p; cudaGetSymbolAddress((void**)&g_xz_p, g_xz);
    float* g_y_p;  cudaGetSymbolAddress((void**)&g_y_p,  g_y);
    float* g_mo_p; cudaGetSymbolAddress((void**)&g_mo_p, g_mo);

    // 1. LayerNorm1 (+ transpose into row-major sequences)
    ln1_kernel<<<BATCH*(LSEQ/32), 256>>>(x, ln1_w, ln1_b);
    // 2. in_proj: (8192,256) @ (1024,256)^T -> (8192,1024)
    gemm_abt<<<dim3((2*DIN)/64, ROWS/64), 256>>>(g_h_p, in_proj, g_xz_p, ROWS, 2*DIN, DM);
    // 3. depthwise conv + SiLU
    conv_kernel<<<ROWS, DIN>>>(conv_w, conv_b);
    // 4. x_proj + dt_proj + softplus
    xproj_kernel<<<ROWS, 256>>>(x_proj, dt_proj, dt_bias);
    // 5. selective scan + gating
    scan_kernel<<<(BATCH*DIN)/8, 128>>>(A_log, Dp);
    // 6. out_proj: (8192,512) @ (256,512)^T -> (8192,256)
    gemm_abt<<<dim3(DM/64, ROWS/64), 256>>>(g_y_p, out_proj, g_mo_p, ROWS, DM, DIN);
    // 7. LayerNorm2 + residual + transpose back
    ln2_kernel<<<BATCH*(LSEQ/32), 256>>>(ln2_w, ln2_b, x, out);
}

// round 2
// speedup vs baseline: 8.5986x; 8.5986x over previous
#include <cuda_runtime.h>
#include <cstdint>

#define BATCH   2
#define DM      256
#define HH      64
#define WW      64
#define LSEQ    (HH*WW)          // 4096
#define DIN     512
#define DSTATE  16
#define DTR     16
#define DCONV   4
#define ROWS    (BATCH*LSEQ)     // 8192
#define NC      128              // chunks per sequence
#define CL      32               // chunk length (NC*CL == LSEQ)

// ---------------- scratch (device globals) ----------------
__device__ float g_h  [ROWS*DM];          // LN1 output
__device__ float g_xz [ROWS*2*DIN];       // in_proj output: [0:512)=xm, [512:1024)=z
__device__ float g_xc [ROWS*DIN];         // conv+silu output
__device__ float g_sp [ROWS*48];          // x_proj output (dt_rank 16 | B 16 | C 16)
__device__ float g_dt [ROWS*DIN];         // softplus(dt)
__device__ float g_y  [ROWS*DIN];         // scan output (gated)
__device__ float g_mo [ROWS*DM];          // out_proj output
// chunked-scan state, layout [b][c][s][d]
__device__ float g_P  [BATCH*NC*DSTATE*DIN];
__device__ float g_E  [BATCH*NC*DSTATE*DIN];
__device__ float g_Hin[BATCH*NC*DSTATE*DIN];

// ---------------- LN1: x (B,C,L) -> g_h (row=b*L+l, 256) ----------------
__global__ void ln1_kernel(const float* __restrict__ x,
                           const float* __restrict__ w,
                           const float* __restrict__ bb) {
    __shared__ float sm[DM*33];
    int b  = blockIdx.x / (LSEQ/32);
    int l0 = (blockIdx.x % (LSEQ/32)) * 32;
    int tid = threadIdx.x;
    int li = tid & 31, c0 = tid >> 5;
    const float* xb = x + (size_t)b*DM*LSEQ;
    #pragma unroll
    for (int c = c0; c < DM; c += 8)
        sm[c*33 + li] = xb[(size_t)c*LSEQ + l0 + li];
    __syncthreads();
    int wid = tid >> 5, lane = tid & 31;
    for (int li2 = wid; li2 < 32; li2 += 8) {
        float s = 0.f, s2 = 0.f, v[8];
        #pragma unroll
        for (int k = 0; k < 8; k++) {
            v[k] = sm[(k*32+lane)*33 + li2];
            s += v[k]; s2 += v[k]*v[k];
        }
        #pragma unroll
        for (int o = 16; o > 0; o >>= 1) {
            s  += __shfl_xor_sync(0xffffffffu, s,  o);
            s2 += __shfl_xor_sync(0xffffffffu, s2, o);
        }
        float mu = s * (1.f/DM);
        float var = s2 * (1.f/DM) - mu*mu;
        float rs = rsqrtf(var + 1e-5f);
        float* orow = g_h + ((size_t)b*LSEQ + l0 + li2)*DM;
        #pragma unroll
        for (int k = 0; k < 8; k++) {
            int c = k*32 + lane;
            orow[c] = (v[k]-mu)*rs*w[c] + bb[c];
        }
    }
}

// -------- GEMM C[M,N] = A[M,K] @ W[N,K]^T ; BM=128,BN=64,BK=16, 8x4/thr ----
__global__ void gemm_tile(const float* __restrict__ A, const float* __restrict__ W,
                          float* __restrict__ C, int M, int N, int K) {
    __shared__ float As[16][128];
    __shared__ float Ws[16][64];
    int bm = blockIdx.y * 128, bn = blockIdx.x * 64;
    int tid = threadIdx.x;                 // 256
    int row0 = (tid >> 4) * 8;             // 0..120
    int col0 = (tid & 15) * 4;             // 0..60
    float acc[8][4] = {};
    for (int k0 = 0; k0 < K; k0 += 16) {
        #pragma unroll
        for (int j = 0; j < 2; j++) {
            int i = tid + j*256;            // 0..511 : 128 rows x 4 f4
            int m = i >> 2, kc = (i & 3) * 4;
            float4 v = *(const float4*)&A[(size_t)(bm+m)*K + k0 + kc];
            As[kc+0][m]=v.x; As[kc+1][m]=v.y; As[kc+2][m]=v.z; As[kc+3][m]=v.w;
        }
        {
            int i = tid;                    // 256 : 64 rows x 4 f4
            int n = i >> 2, kc = (i & 3) * 4;
            float4 v = *(const float4*)&W[(size_t)(bn+n)*K + k0 + kc];
            Ws[kc+0][n]=v.x; Ws[kc+1][n]=v.y; Ws[kc+2][n]=v.z; Ws[kc+3][n]=v.w;
        }
        __syncthreads();
        #pragma unroll
        for (int k = 0; k < 16; k++) {
            float a[8], w[4];
            *(float4*)(a)   = *(const float4*)&As[k][row0];
            *(float4*)(a+4) = *(const float4*)&As[k][row0+4];
            *(float4*)(w)   = *(const float4*)&Ws[k][col0];
            #pragma unroll
            for (int i = 0; i < 8; i++)
                #pragma unroll
                for (int j = 0; j < 4; j++)
                    acc[i][j] += a[i]*w[j];
        }
        __syncthreads();
    }
    #pragma unroll
    for (int i = 0; i < 8; i++) {
        float4 v = make_float4(acc[i][0], acc[i][1], acc[i][2], acc[i][3]);
        *(float4*)&C[(size_t)(bm+row0+i)*N + bn + col0] = v;
    }
}

// ---------------- depthwise causal conv(4) + bias + SiLU ----------------
__global__ void conv_kernel(const float* __restrict__ cw, const float* __restrict__ cb) {
    int r = blockIdx.x;           // b*L + l
    int d = threadIdx.x;          // 0..511
    int l = r & (LSEQ-1);
    float acc = cb[d];
    #pragma unroll
    for (int k = 0; k < DCONV; k++) {
        int ll = l - (DCONV-1) + k;
        if (ll >= 0)
            acc += cw[d*DCONV + k] * g_xz[((size_t)r - (DCONV-1) + k)*(2*DIN) + d];
    }
    g_xc[(size_t)r*DIN + d] = acc / (1.f + __expf(-acc));
}

// -------- x_proj GEMM: g_sp[M,48] = g_xc[M,512] @ W[48,512]^T ----------
__global__ void xp_gemm(const float* __restrict__ W) {
    __shared__ float As[32][64];
    __shared__ float Ws[32][48];
    int bm = blockIdx.x * 64;
    int tid = threadIdx.x;                  // 256
    int tm = (tid >> 4) * 4;                // 0..60
    int tn = (tid & 15) * 3;                // 0..45
    float acc[4][3] = {};
    for (int k0 = 0; k0 < DIN; k0 += 32) {
        #pragma unroll
        for (int j = 0; j < 2; j++) {
            int i = tid + j*256;            // 0..511 : 64 rows x 8 f4
            int m = i >> 3, kc = (i & 7) * 4;
            float4 v = *(const float4*)&g_xc[(size_t)(bm+m)*DIN + k0 + kc];
            As[kc+0][m]=v.x; As[kc+1][m]=v.y; As[kc+2][m]=v.z; As[kc+3][m]=v.w;
        }
        for (int i = tid; i < 384; i += 256) { // 48 rows x 8 f4
            int n = i >> 3, kc = (i & 7) * 4;
            float4 v = *(const float4*)&W[(size_t)n*DIN + k0 + kc];
            Ws[kc+0][n]=v.x; Ws[kc+1][n]=v.y; Ws[kc+2][n]=v.z; Ws[kc+3][n]=v.w;
        }
        __syncthreads();
        #pragma unroll
        for (int k = 0; k < 32; k++) {
            float a[4];
            *(float4*)a = *(const float4*)&As[k][tm];
            float w0 = Ws[k][tn], w1 = Ws[k][tn+1], w2 = Ws[k][tn+2];
            #pragma unroll
            for (int i = 0; i < 4; i++) {
                acc[i][0] += a[i]*w0; acc[i][1] += a[i]*w1; acc[i][2] += a[i]*w2;
            }
        }
        __syncthreads();
    }
    #pragma unroll
    for (int i = 0; i < 4; i++)
        #pragma unroll
        for (int j = 0; j < 3; j++)
            g_sp[(size_t)(bm+tm+i)*48 + tn + j] = acc[i][j];
}

// -------- dt_proj (512x16) + softplus, weights in smem ----------
__global__ void dt_kernel(const float* __restrict__ dpw, const float* __restrict__ dpb) {
    __shared__ float sw[DIN*DTR];   // 32KB
    __shared__ float sp[16*DTR];    // 16 rows
    int r0 = blockIdx.x * 16;
    int tid = threadIdx.x;          // 256
    for (int i = tid; i < DIN*DTR; i += 256) sw[i] = dpw[i];
    {
        int row = tid >> 4, k = tid & 15;
        sp[tid] = g_sp[(size_t)(r0+row)*48 + k];
    }
    __syncthreads();
    for (int i = tid; i < 16*DIN; i += 256) {
        int row = i >> 9, d = i & (DIN-1);
        float s = dpb[d];
        const float* wr = sw + d*DTR;
        const float* pr = sp + row*DTR;
        #pragma unroll
        for (int k = 0; k < DTR; k++) s += wr[k]*pr[k];
        g_dt[(size_t)(r0+row)*DIN + d] = (s > 20.f) ? s : log1pf(__expf(s));
    }
}

// -------- scan pass 1: per-chunk decay product P and local end-state E ----
__global__ void scan_pass1(const float* __restrict__ A_log) {
    __shared__ float sB[CL*DSTATE];
    int bc = blockIdx.x >> 2;            // b*NC + c
    int db = blockIdx.x & 3;
    int b = bc / NC, c = bc % NC;
    int d = db*128 + threadIdx.x;
    int r0 = b*LSEQ + c*CL;
    for (int i = threadIdx.x; i < CL*DSTATE; i += 128) {
        int row = i >> 4, s = i & 15;
        sB[i] = g_sp[(size_t)(r0+row)*48 + 16 + s];
    }
    __syncthreads();
    float aA[DSTATE];
    #pragma unroll
    for (int s = 0; s < DSTATE; s++) aA[s] = -__expf(A_log[d*DSTATE + s]);
    float h[DSTATE] = {}, P[DSTATE];
    #pragma unroll
    for (int s = 0; s < DSTATE; s++) P[s] = 1.f;
    for (int l = 0; l < CL; l++) {
        size_t r = r0 + l;
        float dt = g_dt[r*DIN + d];
        float xv = g_xc[r*DIN + d];
        float dtx = dt * xv;
        #pragma unroll
        for (int s = 0; s < DSTATE; s++) {
            float da = __expf(dt * aA[s]);
            P[s] *= da;
            h[s] = h[s]*da + dtx*sB[l*DSTATE + s];
        }
    }
    size_t base = (size_t)bc * (DSTATE*DIN) + d;
    #pragma unroll
    for (int s = 0; s < DSTATE; s++) {
        g_P[base + (size_t)s*DIN] = P[s];
        g_E[base + (size_t)s*DIN] = h[s];
    }
}

// -------- scan pass 2: serial carry over chunks ----------
__global__ void scan_pass2() {
    int t = blockIdx.x*256 + threadIdx.x;   // 0..16383 : b*8192 + s*512 + d
    int b = t >> 13;
    int rem = t & 8191;
    float carry = 0.f;
    for (int c = 0; c < NC; c++) {
        size_t idx = (size_t)(b*NC + c)*8192 + rem;
        g_Hin[idx] = carry;
        carry = carry * g_P[idx] + g_E[idx];
    }
}

// -------- scan pass 3: replay chunk with carry-in, emit gated y ----------
__global__ void scan_pass3(const float* __restrict__ A_log, const float* __restrict__ Dp) {
    __shared__ float sBC[CL*32];
    int bc = blockIdx.x >> 2;
    int db = blockIdx.x & 3;
    int b = bc / NC, c = bc % NC;
    int d = db*128 + threadIdx.x;
    int r0 = b*LSEQ + c*CL;
    for (int i = threadIdx.x; i < CL*32; i += 128) {
        int row = i >> 5, col = i & 31;
        sBC[i] = g_sp[(size_t)(r0+row)*48 + 16 + col];
    }
    __syncthreads();
    float aA[DSTATE], h[DSTATE];
    size_t base = (size_t)bc * (DSTATE*DIN) + d;
    #pragma unroll
    for (int s = 0; s < DSTATE; s++) {
        aA[s] = -__expf(A_log[d*DSTATE + s]);
        h[s]  = g_Hin[base + (size_t)s*DIN];
    }
    float Dd = Dp[d];
    for (int l = 0; l < CL; l++) {
        size_t r = r0 + l;
        float dt = g_dt[r*DIN + d];
        float xv = g_xc[r*DIN + d];
        float dtx = dt * xv;
        float y = 0.f;
        #pragma unroll
        for (int s = 0; s < DSTATE; s++) {
            float da = __expf(dt * aA[s]);
            h[s] = h[s]*da + dtx*sBC[l*32 + s];
            y += h[s] * sBC[l*32 + 16 + s];
        }
        float z = g_xz[r*(2*DIN) + DIN + d];
        g_y[r*DIN + d] = (y + xv*Dd) * (z / (1.f + __expf(-z)));
    }
}

// ---------------- LN2 + residual + transpose back to (B,C,H,W) ----------
__global__ void ln2_kernel(const float* __restrict__ w, const float* __restrict__ bb,
                           const float* __restrict__ x, float* __restrict__ out) {
    __shared__ float sm[DM*33];
    int b  = blockIdx.x / (LSEQ/32);
    int l0 = (blockIdx.x % (LSEQ/32)) * 32;
    int tid = threadIdx.x;
    const float* mo = g_mo + ((size_t)b*LSEQ + l0)*DM;
    for (int i = tid; i < 32*DM; i += 256) {
        int li = i >> 8, c = i & 255;
        sm[c*33 + li] = mo[li*DM + c];
    }
    __syncthreads();
    int wid = tid >> 5, lane = tid & 31;
    for (int li2 = wid; li2 < 32; li2 += 8) {
        float s = 0.f, s2 = 0.f, v[8];
        #pragma unroll
        for (int k = 0; k < 8; k++) {
            v[k] = sm[(k*32+lane)*33 + li2];
            s += v[k]; s2 += v[k]*v[k];
        }
        #pragma unroll
        for (int o = 16; o > 0; o >>= 1) {
            s  += __shfl_xor_sync(0xffffffffu, s,  o);
            s2 += __shfl_xor_sync(0xffffffffu, s2, o);
        }
        float mu = s * (1.f/DM);
        float var = s2 * (1.f/DM) - mu*mu;
        float rs = rsqrtf(var + 1e-5f);
        #pragma unroll
        for (int k = 0; k < 8; k++) {
            int c = k*32 + lane;
            sm[c*33 + li2] = (v[k]-mu)*rs*w[c] + bb[c];
        }
    }
    __syncthreads();
    int li = tid & 31, c0 = tid >> 5;
    const float* xb = x + (size_t)b*DM*LSEQ;
    float* ob = out + (size_t)b*DM*LSEQ;
    #pragma unroll
    for (int c = c0; c < DM; c += 8) {
        size_t idx = (size_t)c*LSEQ + l0 + li;
        ob[idx] = xb[idx] + sm[c*33 + li];
    }
}

// ---------------- launch ----------------
extern "C" void kernel_launch(void* const* d_in, const int* in_sizes, int n_in,
                              void* d_out, int out_size) {
    const float* x        = (const float*)d_in[0];
    const float* ln1_w    = (const float*)d_in[1];
    const float* ln1_b    = (const float*)d_in[2];
    const float* ln2_w    = (const float*)d_in[3];
    const float* ln2_b    = (const float*)d_in[4];
    const float* in_proj  = (const float*)d_in[5];
    const float* conv_w   = (const float*)d_in[6];
    const float* conv_b   = (const float*)d_in[7];
    const float* x_proj   = (const float*)d_in[8];
    const float* dt_proj  = (const float*)d_in[9];
    const float* dt_bias  = (const float*)d_in[10];
    const float* A_log    = (const float*)d_in[11];
    const float* Dp       = (const float*)d_in[12];
    const float* out_proj = (const float*)d_in[13];
    float* out = (float*)d_out;

    float* g_h_p;  cudaGetSymbolAddress((void**)&g_h_p,  g_h);
    float* g_xz_p; cudaGetSymbolAddress((void**)&g_xz_p, g_xz);
    float* g_y_p;  cudaGetSymbolAddress((void**)&g_y_p,  g_y);
    float* g_mo_p; cudaGetSymbolAddress((void**)&g_mo_p, g_mo);

    // 1. LayerNorm1 (+ transpose into row-major sequences)
    ln1_kernel<<<BATCH*(LSEQ/32), 256>>>(x, ln1_w, ln1_b);
    // 2. in_proj: (8192,256) @ (1024,256)^T -> (8192,1024)
    gemm_tile<<<dim3((2*DIN)/64, ROWS/128), 256>>>(g_h_p, in_proj, g_xz_p, ROWS, 2*DIN, DM);
    // 3. depthwise conv + SiLU
    conv_kernel<<<ROWS, DIN>>>(conv_w, conv_b);
    // 4. x_proj GEMM -> g_sp
    xp_gemm<<<ROWS/64, 256>>>(x_proj);
    // 5. dt_proj + softplus
    dt_kernel<<<ROWS/16, 256>>>(dt_proj, dt_bias);
    // 6. chunked selective scan
    scan_pass1<<<BATCH*NC*4, 128>>>(A_log);
    scan_pass2<<<(BATCH*DIN*DSTATE)/256, 256>>>();
    scan_pass3<<<BATCH*NC*4, 128>>>(A_log, Dp);
    // 7. out_proj: (8192,512) @ (256,512)^T -> (8192,256)
    gemm_tile<<<dim3(DM/64, ROWS/128), 256>>>(g_y_p, out_proj, g_mo_p, ROWS, DM, DIN);
    // 8. LayerNorm2 + residual + transpose back
    ln2_kernel<<<BATCH*(LSEQ/32), 256>>>(ln2_w, ln2_b, x, out);
}

// round 5
// speedup vs baseline: 11.5833x; 1.3471x over previous
#include <cuda_runtime.h>
#include <cuda_bf16.h>
#include <cstdint>

#define BATCH   2
#define DM      256
#define HH      64
#define WW      64
#define LSEQ    (HH*WW)          // 4096
#define DIN     512
#define DSTATE  16
#define DTR     16
#define DCONV   4
#define ROWS    (BATCH*LSEQ)     // 8192
#define NC      128              // chunks per sequence
#define CL      32               // chunk length

// ---------------- scratch (device globals) ----------------
__device__ __align__(16) __nv_bfloat16 g_hh [ROWS*DM];   // ln1 out hi
__device__ __align__(16) __nv_bfloat16 g_hl [ROWS*DM];   // ln1 out lo
__device__ __align__(16) __nv_bfloat16 g_wih[2*DIN*DM];  // in_proj hi
__device__ __align__(16) __nv_bfloat16 g_wil[2*DIN*DM];
__device__ __align__(16) __nv_bfloat16 g_woh[DM*DIN];    // out_proj hi
__device__ __align__(16) __nv_bfloat16 g_wol[DM*DIN];
__device__ __align__(16) __nv_bfloat16 g_yh [ROWS*DIN];  // scan out hi
__device__ __align__(16) __nv_bfloat16 g_yl [ROWS*DIN];
__device__ __align__(16) float g_xz [ROWS*2*DIN];        // in_proj out
__device__ __align__(16) float g_xc [ROWS*DIN];          // conv+silu out
__device__ __align__(16) float g_sp [ROWS*48];           // x_proj out
__device__ __align__(16) float g_dt [ROWS*DIN];          // softplus(dt)
__device__ __align__(16) float g_mo [ROWS*DM];           // out_proj out
__device__ float g_P  [BATCH*NC*DSTATE*DIN];
__device__ float g_E  [BATCH*NC*DSTATE*DIN];
__device__ float g_Hin[BATCH*NC*DSTATE*DIN];

// ---------------- weight split fp32 -> bf16 hi/lo ----------------
__global__ void cvt_kernel(const float* __restrict__ src,
                           __nv_bfloat16* __restrict__ dh,
                           __nv_bfloat16* __restrict__ dl, int n) {
    int i = blockIdx.x*256 + threadIdx.x;
    if (i < n) {
        float v = src[i];
        __nv_bfloat16 h = __float2bfloat16(v);
        dh[i] = h;
        dl[i] = __float2bfloat16(v - __bfloat162float(h));
    }
}

// ---------------- LN1: x (B,C,L) -> g_hh/g_hl (row, 256) ----------------
__global__ void ln1_kernel(const float* __restrict__ x,
                           const float* __restrict__ w,
                           const float* __restrict__ bb) {
    __shared__ float sm[DM*33];
    int b  = blockIdx.x / (LSEQ/32);
    int l0 = (blockIdx.x % (LSEQ/32)) * 32;
    int tid = threadIdx.x;
    int li = tid & 31, c0 = tid >> 5;
    const float* xb = x + (size_t)b*DM*LSEQ;
    #pragma unroll
    for (int c = c0; c < DM; c += 8)
        sm[c*33 + li] = xb[(size_t)c*LSEQ + l0 + li];
    __syncthreads();
    int wid = tid >> 5, lane = tid & 31;
    for (int li2 = wid; li2 < 32; li2 += 8) {
        float s = 0.f, s2 = 0.f, v[8];
        #pragma unroll
        for (int k = 0; k < 8; k++) {
            v[k] = sm[(k*32+lane)*33 + li2];
            s += v[k]; s2 += v[k]*v[k];
        }
        #pragma unroll
        for (int o = 16; o > 0; o >>= 1) {
            s  += __shfl_xor_sync(0xffffffffu, s,  o);
            s2 += __shfl_xor_sync(0xffffffffu, s2, o);
        }
        float mu = s * (1.f/DM);
        float var = s2 * (1.f/DM) - mu*mu;
        float rs = rsqrtf(var + 1e-5f);
        size_t ro = ((size_t)b*LSEQ + l0 + li2)*DM;
        #pragma unroll
        for (int k = 0; k < 8; k++) {
            int c = k*32 + lane;
            float val = (v[k]-mu)*rs*w[c] + bb[c];
            __nv_bfloat16 h = __float2bfloat16(val);
            g_hh[ro + c] = h;
            g_hl[ro + c] = __float2bfloat16(val - __bfloat162float(h));
        }
    }
}

// ======== HMMA bf16 split-2 GEMM: C[M,N] fp32 = A @ W^T ========
__device__ __forceinline__ void ldsm_x4(uint32_t* r, uint32_t addr) {
    asm volatile("ldmatrix.sync.aligned.m8n8.x4.shared.b16 {%0,%1,%2,%3}, [%4];"
        : "=r"(r[0]),"=r"(r[1]),"=r"(r[2]),"=r"(r[3]) : "r"(addr));
}
__device__ __forceinline__ void mma_bf16(float* c, const uint32_t* a, const uint32_t* b) {
    asm volatile("mma.sync.aligned.m16n8k16.row.col.f32.bf16.bf16.f32 "
        "{%0,%1,%2,%3},{%4,%5,%6,%7},{%8,%9},{%0,%1,%2,%3};"
        : "+f"(c[0]),"+f"(c[1]),"+f"(c[2]),"+f"(c[3])
        : "r"(a[0]),"r"(a[1]),"r"(a[2]),"r"(a[3]), "r"(b[0]),"r"(b[1]));
}

#define RS 40   // smem row stride in bf16 (32 data + 8 pad); 80B rows, 16B-aligned

__global__ __launch_bounds__(256)
void gemm_bf16(const __nv_bfloat16* __restrict__ Ah,
               const __nv_bfloat16* __restrict__ Al,
               const __nv_bfloat16* __restrict__ Wh,
               const __nv_bfloat16* __restrict__ Wl,
               float* __restrict__ C, int M, int N, int K) {
    __shared__ __align__(16) __nv_bfloat16 sAh[128*RS];
    __shared__ __align__(16) __nv_bfloat16 sAl[128*RS];
    __shared__ __align__(16) __nv_bfloat16 sWh[128*RS];
    __shared__ __align__(16) __nv_bfloat16 sWl[128*RS];
    int tid = threadIdx.x;
    int lane = tid & 31, wid = tid >> 5;
    int wm = wid >> 1, wn = wid & 1;          // warp grid 4x2 (32m x 64n)
    int bm = blockIdx.y * 128, bn = blockIdx.x * 128;

    float acc[2][8][4];
    #pragma unroll
    for (int i = 0; i < 2; i++)
        #pragma unroll
        for (int j = 0; j < 8; j++)
            #pragma unroll
            for (int q = 0; q < 4; q++) acc[i][j][q] = 0.f;

    // ldmatrix lane->address maps (elements)
    int a_row = (lane & 15), a_colsel = (lane >> 4) << 3;          // A: rows in lane[0:4), k-block in lane[4]
    int b_row = ((lane >> 4) << 3) + (lane & 7);                   // B: n in lanes {0-7 | 16-23}
    int b_colsel = ((lane >> 3) & 1) << 3;                         //    k-block in lane[3]

    for (int k0 = 0; k0 < K; k0 += 32) {
        #pragma unroll
        for (int j = 0; j < 2; j++) {
            int v = tid + j*256;                 // 0..511
            int row = v >> 2, u = (v & 3) * 8;
            *(uint4*)&sAh[row*RS + u] = *(const uint4*)&Ah[(size_t)(bm+row)*K + k0 + u];
            *(uint4*)&sAl[row*RS + u] = *(const uint4*)&Al[(size_t)(bm+row)*K + k0 + u];
            *(uint4*)&sWh[row*RS + u] = *(const uint4*)&Wh[(size_t)(bn+row)*K + k0 + u];
            *(uint4*)&sWl[row*RS + u] = *(const uint4*)&Wl[(size_t)(bn+row)*K + k0 + u];
        }
        __syncthreads();
        #pragma unroll
        for (int kk = 0; kk < 2; kk++) {
            int kc = kk*16;
            uint32_t ah[2][4], bh[4][4];
            #pragma unroll
            for (int mi = 0; mi < 2; mi++) {
                uint32_t ad = (uint32_t)__cvta_generic_to_shared(
                    &sAh[(wm*32 + mi*16 + a_row)*RS + kc + a_colsel]);
                ldsm_x4(ah[mi], ad);
            }
            #pragma unroll
            for (int nb = 0; nb < 4; nb++) {
                uint32_t ad = (uint32_t)__cvta_generic_to_shared(
                    &sWh[(wn*64 + nb*16 + b_row)*RS + kc + b_colsel]);
                ldsm_x4(bh[nb], ad);
            }
            // term 1: Ah * Wh
            #pragma unroll
            for (int mi = 0; mi < 2; mi++)
                #pragma unroll
                for (int nb = 0; nb < 4; nb++) {
                    mma_bf16(acc[mi][nb*2],   ah[mi], bh[nb]);
                    mma_bf16(acc[mi][nb*2+1], ah[mi], bh[nb]+2);
                }
            // term 2: Ah * Wl
            #pragma unroll
            for (int nb = 0; nb < 4; nb++) {
                uint32_t bl[4];
                uint32_t ad = (uint32_t)__cvta_generic_to_shared(
                    &sWl[(wn*64 + nb*16 + b_row)*RS + kc + b_colsel]);
                ldsm_x4(bl, ad);
                #pragma unroll
                for (int mi = 0; mi < 2; mi++) {
                    mma_bf16(acc[mi][nb*2],   ah[mi], bl);
                    mma_bf16(acc[mi][nb*2+1], ah[mi], bl+2);
                }
            }
            // term 3: Al * Wh
            #pragma unroll
            for (int mi = 0; mi < 2; mi++) {
                uint32_t al[4];
                uint32_t ad = (uint32_t)__cvta_generic_to_shared(
                    &sAl[(wm*32 + mi*16 + a_row)*RS + kc + a_colsel]);
                ldsm_x4(al, ad);
                #pragma unroll
                for (int nb = 0; nb < 4; nb++) {
                    mma_bf16(acc[mi][nb*2],   al, bh[nb]);
                    mma_bf16(acc[mi][nb*2+1], al, bh[nb]+2);
                }
            }
        }
        __syncthreads();
    }
    // epilogue: c0,c1 -> (row, col..col+1); c2,c3 -> (row+8, ...)
    #pragma unroll
    for (int mi = 0; mi < 2; mi++)
        #pragma unroll
        for (int nb = 0; nb < 4; nb++)
            #pragma unroll
            for (int sub = 0; sub < 2; sub++) {
                float* c = acc[mi][nb*2 + sub];
                int row = bm + wm*32 + mi*16 + (lane >> 2);
                int col = bn + wn*64 + nb*16 + sub*8 + (lane & 3)*2;
                *(float2*)&C[(size_t)row*N + col]     = make_float2(c[0], c[1]);
                *(float2*)&C[(size_t)(row+8)*N + col] = make_float2(c[2], c[3]);
            }
}

// ---------------- depthwise causal conv(4) + bias + SiLU ----------------
__global__ void conv_kernel(const float* __restrict__ cw, const float* __restrict__ cb) {
    int r = blockIdx.x;
    int d = threadIdx.x;
    int l = r & (LSEQ-1);
    float acc = cb[d];
    #pragma unroll
    for (int k = 0; k < DCONV; k++) {
        int ll = l - (DCONV-1) + k;
        if (ll >= 0)
            acc += cw[d*DCONV + k] * g_xz[((size_t)r - (DCONV-1) + k)*(2*DIN) + d];
    }
    g_xc[(size_t)r*DIN + d] = acc / (1.f + __expf(-acc));
}

// -------- x_proj GEMM: g_sp[M,48] = g_xc[M,512] @ W[48,512]^T ; BM=32 ----
__global__ void xp_gemm(const float* __restrict__ W) {
    __shared__ float As[32][36];   // stride 36 floats = 144B (16B-aligned float4 rows)
    __shared__ float Ws[32][48];
    int bm = blockIdx.x * 32;
    int tid = threadIdx.x;                  // 128
    int tm = (tid >> 4) * 4;
    int tn = (tid & 15) * 3;
    float acc[4][3] = {};
    for (int k0 = 0; k0 < DIN; k0 += 32) {
        #pragma unroll
        for (int j = 0; j < 2; j++) {
            int i = tid + j*128;
            int m = i >> 3, kc = (i & 7) * 4;
            float4 v = *(const float4*)&g_xc[(size_t)(bm+m)*DIN + k0 + kc];
            As[kc+0][m]=v.x; As[kc+1][m]=v.y; As[kc+2][m]=v.z; As[kc+3][m]=v.w;
        }
        #pragma unroll
        for (int j = 0; j < 3; j++) {
            int i = tid + j*128;
            int n = i >> 3, kc = (i & 7) * 4;
            float4 v = *(const float4*)&W[(size_t)n*DIN + k0 + kc];
            Ws[kc+0][n]=v.x; Ws[kc+1][n]=v.y; Ws[kc+2][n]=v.z; Ws[kc+3][n]=v.w;
        }
        __syncthreads();
        #pragma unroll
        for (int k = 0; k < 32; k++) {
            float a[4];
            *(float4*)a = *(const float4*)&As[k][tm];
            float w0 = Ws[k][tn], w1 = Ws[k][tn+1], w2 = Ws[k][tn+2];
            #pragma unroll
            for (int i = 0; i < 4; i++) {
                acc[i][0] += a[i]*w0; acc[i][1] += a[i]*w1; acc[i][2] += a[i]*w2;
            }
        }
        __syncthreads();
    }
    #pragma unroll
    for (int i = 0; i < 4; i++)
        #pragma unroll
        for (int j = 0; j < 3; j++)
            g_sp[(size_t)(bm+tm+i)*48 + tn + j] = acc[i][j];
}

// -------- dt_proj (512x16) + softplus ----------
__global__ void dt_kernel(const float* __restrict__ dpw, const float* __restrict__ dpb) {
    __shared__ float sw[DIN*DTR];
    __shared__ float sp[16*DTR];
    int r0 = blockIdx.x * 16;
    int tid = threadIdx.x;          // 256
    for (int i = tid; i < DIN*DTR; i += 256) sw[i] = dpw[i];
    {
        int row = tid >> 4, k = tid & 15;
        sp[tid] = g_sp[(size_t)(r0+row)*48 + k];
    }
    __syncthreads();
    for (int i = tid; i < 16*DIN; i += 256) {
        int row = i >> 9, d = i & (DIN-1);
        float s = dpb[d];
        const float* wr = sw + d*DTR;
        const float* pr = sp + row*DTR;
        #pragma unroll
        for (int k = 0; k < DTR; k++) s += wr[k]*pr[k];
        g_dt[(size_t)(r0+row)*DIN + d] = (s > 20.f) ? s : log1pf(__expf(s));
    }
}

// -------- scan pass 1: per-chunk decay product P and local end-state E ----
__global__ void scan_pass1(const float* __restrict__ A_log) {
    __shared__ float sB[CL*DSTATE];
    int bc = blockIdx.x >> 2;
    int db = blockIdx.x & 3;
    int b = bc / NC, c = bc % NC;
    int d = db*128 + threadIdx.x;
    int r0 = b*LSEQ + c*CL;
    for (int i = threadIdx.x; i < CL*DSTATE; i += 128) {
        int row = i >> 4, s = i & 15;
        sB[i] = g_sp[(size_t)(r0+row)*48 + 16 + s];
    }
    __syncthreads();
    float aA[DSTATE];
    #pragma unroll
    for (int s = 0; s < DSTATE; s++) aA[s] = -__expf(A_log[d*DSTATE + s]);
    float h[DSTATE] = {};
    float dtsum = 0.f;
    for (int l = 0; l < CL; l++) {
        size_t r = r0 + l;
        float dt = g_dt[r*DIN + d];
        float xv = g_xc[r*DIN + d];
        float dtx = dt * xv;
        dtsum += dt;
        #pragma unroll
        for (int s = 0; s < DSTATE; s++) {
            float da = __expf(dt * aA[s]);
            h[s] = h[s]*da + dtx*sB[l*DSTATE + s];
        }
    }
    size_t base = (size_t)bc * (DSTATE*DIN) + d;
    #pragma unroll
    for (int s = 0; s < DSTATE; s++) {
        g_P[base + (size_t)s*DIN] = __expf(dtsum * aA[s]);
        g_E[base + (size_t)s*DIN] = h[s];
    }
}

// -------- scan pass 2: serial carry over chunks ----------
__global__ void scan_pass2() {
    int t = blockIdx.x*256 + threadIdx.x;
    int b = t >> 13;
    int rem = t & 8191;
    float carry = 0.f;
    for (int c = 0; c < NC; c++) {
        size_t idx = (size_t)(b*NC + c)*8192 + rem;
        g_Hin[idx] = carry;
        carry = carry * g_P[idx] + g_E[idx];
    }
}

// -------- scan pass 3: replay with carry-in, emit gated y (bf16 hi/lo) ----
__global__ void scan_pass3(const float* __restrict__ A_log, const float* __restrict__ Dp) {
    __shared__ float sBC[CL*32];
    int bc = blockIdx.x >> 2;
    int db = blockIdx.x & 3;
    int b = bc / NC, c = bc % NC;
    int d = db*128 + threadIdx.x;
    int r0 = b*LSEQ + c*CL;
    for (int i = threadIdx.x; i < CL*32; i += 128) {
        int row = i >> 5, col = i & 31;
        sBC[i] = g_sp[(size_t)(r0+row)*48 + 16 + col];
    }
    __syncthreads();
    float aA[DSTATE], h[DSTATE];
    size_t base = (size_t)bc * (DSTATE*DIN) + d;
    #pragma unroll
    for (int s = 0; s < DSTATE; s++) {
        aA[s] = -__expf(A_log[d*DSTATE + s]);
        h[s]  = g_Hin[base + (size_t)s*DIN];
    }
    float Dd = Dp[d];
    for (int l = 0; l < CL; l++) {
        size_t r = r0 + l;
        float dt = g_dt[r*DIN + d];
        float xv = g_xc[r*DIN + d];
        float dtx = dt * xv;
        float y = 0.f;
        #pragma unroll
        for (int s = 0; s < DSTATE; s++) {
            float da = __expf(dt * aA[s]);
            h[s] = h[s]*da + dtx*sBC[l*32 + s];
            y += h[s] * sBC[l*32 + 16 + s];
        }
        float z = g_xz[r*(2*DIN) + DIN + d];
        float val = (y + xv*Dd) * (z / (1.f + __expf(-z)));
        __nv_bfloat16 hh = __float2bfloat16(val);
        g_yh[r*DIN + d] = hh;
        g_yl[r*DIN + d] = __float2bfloat16(val - __bfloat162float(hh));
    }
}

// ---------------- LN2 + residual + transpose back to (B,C,H,W) ----------
__global__ void ln2_kernel(const float* __restrict__ w, const float* __restrict__ bb,
                           const float* __restrict__ x, float* __restrict__ out) {
    __shared__ float sm[DM*33];
    int b  = blockIdx.x / (LSEQ/32);
    int l0 = (blockIdx.x % (LSEQ/32)) * 32;
    int tid = threadIdx.x;
    const float* mo = g_mo + ((size_t)b*LSEQ + l0)*DM;
    for (int i = tid; i < 32*DM; i += 256) {
        int li = i >> 8, c = i & 255;
        sm[c*33 + li] = mo[li*DM + c];
    }
    __syncthreads();
    int wid = tid >> 5, lane = tid & 31;
    for (int li2 = wid; li2 < 32; li2 += 8) {
        float s = 0.f, s2 = 0.f, v[8];
        #pragma unroll
        for (int k = 0; k < 8; k++) {
            v[k] = sm[(k*32+lane)*33 + li2];
            s += v[k]; s2 += v[k]*v[k];
        }
        #pragma unroll
        for (int o = 16; o > 0; o >>= 1) {
            s  += __shfl_xor_sync(0xffffffffu, s,  o);
            s2 += __shfl_xor_sync(0xffffffffu, s2, o);
        }
        float mu = s * (1.f/DM);
        float var = s2 * (1.f/DM) - mu*mu;
        float rs = rsqrtf(var + 1e-5f);
        #pragma unroll
        for (int k = 0; k < 8; k++) {
            int c = k*32 + lane;
            sm[c*33 + li2] = (v[k]-mu)*rs*w[c] + bb[c];
        }
    }
    __syncthreads();
    int li = tid & 31, c0 = tid >> 5;
    const float* xb = x + (size_t)b*DM*LSEQ;
    float* ob = out + (size_t)b*DM*LSEQ;
    #pragma unroll
    for (int c = c0; c < DM; c += 8) {
        size_t idx = (size_t)c*LSEQ + l0 + li;
        ob[idx] = xb[idx] + sm[c*33 + li];
    }
}

// ---------------- launch ----------------
extern "C" void kernel_launch(void* const* d_in, const int* in_sizes, int n_in,
                              void* d_out, int out_size) {
    const float* x        = (const float*)d_in[0];
    const float* ln1_w    = (const float*)d_in[1];
    const float* ln1_b    = (const float*)d_in[2];
    const float* ln2_w    = (const float*)d_in[3];
    const float* ln2_b    = (const float*)d_in[4];
    const float* in_proj  = (const float*)d_in[5];
    const float* conv_w   = (const float*)d_in[6];
    const float* conv_b   = (const float*)d_in[7];
    const float* x_proj   = (const float*)d_in[8];
    const float* dt_proj  = (const float*)d_in[9];
    const float* dt_bias  = (const float*)d_in[10];
    const float* A_log    = (const float*)d_in[11];
    const float* Dp       = (const float*)d_in[12];
    const float* out_proj = (const float*)d_in[13];
    float* out = (float*)d_out;

    __nv_bfloat16 *hh_p, *hl_p, *wih_p, *wil_p, *woh_p, *wol_p, *yh_p, *yl_p;
    float *xz_p, *mo_p;
    cudaGetSymbolAddress((void**)&hh_p,  g_hh);
    cudaGetSymbolAddress((void**)&hl_p,  g_hl);
    cudaGetSymbolAddress((void**)&wih_p, g_wih);
    cudaGetSymbolAddress((void**)&wil_p, g_wil);
    cudaGetSymbolAddress((void**)&woh_p, g_woh);
    cudaGetSymbolAddress((void**)&wol_p, g_wol);
    cudaGetSymbolAddress((void**)&yh_p,  g_yh);
    cudaGetSymbolAddress((void**)&yl_p,  g_yl);
    cudaGetSymbolAddress((void**)&xz_p,  g_xz);
    cudaGetSymbolAddress((void**)&mo_p,  g_mo);

    // 0. split weights to bf16 hi/lo
    cvt_kernel<<<(2*DIN*DM)/256, 256>>>(in_proj, wih_p, wil_p, 2*DIN*DM);
    cvt_kernel<<<(DM*DIN)/256, 256>>>(out_proj, woh_p, wol_p, DM*DIN);
    // 1. LayerNorm1 -> bf16 hi/lo rows
    ln1_kernel<<<BATCH*(LSEQ/32), 256>>>(x, ln1_w, ln1_b);
    // 2. in_proj (HMMA split-2): (8192,256)x(1024,256)^T -> g_xz
    gemm_bf16<<<dim3((2*DIN)/128, ROWS/128), 256>>>(hh_p, hl_p, wih_p, wil_p,
                                                    xz_p, ROWS, 2*DIN, DM);
    // 3. depthwise conv + SiLU
    conv_kernel<<<ROWS, DIN>>>(conv_w, conv_b);
    // 4. x_proj
    xp_gemm<<<ROWS/32, 128>>>(x_proj);
    // 5. dt_proj + softplus
    dt_kernel<<<ROWS/16, 256>>>(dt_proj, dt_bias);
    // 6. chunked selective scan
    scan_pass1<<<BATCH*NC*4, 128>>>(A_log);
    scan_pass2<<<(BATCH*DIN*DSTATE)/256, 256>>>();
    scan_pass3<<<BATCH*NC*4, 128>>>(A_log, Dp);
    // 7. out_proj (HMMA split-2): (8192,512)x(256,512)^T -> g_mo
    gemm_bf16<<<dim3(DM/128, ROWS/128), 256>>>(yh_p, yl_p, woh_p, wol_p,
                                               mo_p, ROWS, DM, DIN);
    // 8. LayerNorm2 + residual + transpose back
    ln2_kernel<<<BATCH*(LSEQ/32), 256>>>(ln2_w, ln2_b, x, out);
}